// round 6
// baseline (speedup 1.0000x reference)
#include <cuda_runtime.h>
#include <cstdint>

// Problem constants
#define BDIM   16
#define NDIM   128
#define EDIM   127
#define MDIM   16
#define BN     2048                 // B*N
#define BNE    260096               // B*N*E

#define CK_THREADS 1024
#define CK_NODES   16
#define CK_BLOCKS  (BN / CK_NODES)  // 128

// Smem layout (floats). W3 slices XOR-swizzled (no padding) -> conflict-free LDS.128
#define OFF_WALL   0                          // 6 * 256 * 32 = 49152
#define OFF_B3     (OFF_WALL + 49152)         // 1536
#define OFF_H2     (OFF_B3 + 1536)            // 2048
#define OFF_S0     (OFF_H2 + 2048)            // 256
#define OFF_C00    (OFF_S0 + 256)             // 256
#define OFF_WS1    (OFF_C00 + 256)            // 256
#define OFF_V11    (OFF_WS1 + 256)            // 2304
#define OFF_B01    (OFF_V11 + 2304)           // 64
#define OFF_MSG    (OFF_B01 + 64)             // 1024
#define SMEM_FLOATS (OFF_MSG + 1024)          // 56896
#define SMEM_BYTES (SMEM_FLOATS * 4)          // 227584

#define OUT1_BASE4 1040384   // (BNE*16)/4

__device__ __forceinline__ float warp_sum(float v) {
    v += __shfl_xor_sync(0xffffffffu, v, 16);
    v += __shfl_xor_sync(0xffffffffu, v, 8);
    v += __shfl_xor_sync(0xffffffffu, v, 4);
    v += __shfl_xor_sync(0xffffffffu, v, 2);
    v += __shfl_xor_sync(0xffffffffu, v, 1);
    return v;
}

#define DOT4(acc, h, wv) do { \
    acc = fmaf((h).x, (wv).x, acc); \
    acc = fmaf((h).y, (wv).y, acc); \
    acc = fmaf((h).z, (wv).z, acc); \
    acc = fmaf((h).w, (wv).w, acc); } while (0)

extern "C" __global__ void __launch_bounds__(CK_THREADS, 1)
fused_kernel(const float* __restrict__ r,
             const float* __restrict__ src0,
             const float* __restrict__ src1,
             const float* __restrict__ b00g,
             const float* __restrict__ b01g,
             const float* __restrict__ b10g,
             const float* __restrict__ b11g,
             const float* __restrict__ w1,
             const float* __restrict__ b1,
             const float* __restrict__ g1,
             const float* __restrict__ be1,
             const float* __restrict__ w2,
             const float* __restrict__ b2,
             const float* __restrict__ g2,
             const float* __restrict__ be2,
             const float* __restrict__ w300, const float* __restrict__ b300,
             const float* __restrict__ w301, const float* __restrict__ b301,
             const float* __restrict__ w310, const float* __restrict__ b310,
             const float* __restrict__ w311, const float* __restrict__ b311,
             float4* __restrict__ out)
{
    extern __shared__ float sm[];
    float* Wall  = sm + OFF_WALL;
    float* b3a   = sm + OFF_B3;
    float* h2s   = sm + OFF_H2;
    float* s0s   = sm + OFF_S0;
    float* c00s  = sm + OFF_C00;
    float* ws1s  = sm + OFF_WS1;
    float* v11s  = sm + OFF_V11;
    float* b01sm = sm + OFF_B01;
    float* msgAcc= sm + OFF_MSG;

    const int t    = threadIdx.x;
    const int lane = t & 31;
    const int w    = t >> 5;           // 0..31
    const int blk  = blockIdx.x;

    // ---- zero message accumulators (one element per thread) ----
    msgAcc[t] = 0.f;

    // ---- stage ALL six W3 channel slices, permuted (i fastest) + XOR-swizzled ----
    float4* Wall4 = (float4*)Wall;
    for (int d4 = t; d4 < 12288; d4 += CK_THREADS) {
        int ch  = d4 >> 11;            // 0..5
        int rem = d4 & 2047;
        int rowp = rem >> 3;
        int k4   = rem & 7;
        int ii = rowp & 15, g = rowp >> 4;
        const float4* src;
        int srow;
        if (ch >= 3) { src = (const float4*)w311; srow = ii * 48 + (ch - 3) * 16 + g; }
        else {
            src = (ch == 0) ? (const float4*)w300
                : (ch == 1) ? (const float4*)w301
                            : (const float4*)w310;
            srow = ii * 16 + g;
        }
        Wall4[ch * 2048 + rowp * 8 + (k4 ^ (rowp & 7))] = src[srow * 8 + k4];
    }
    for (int idx = t; idx < 1536; idx += CK_THREADS) {
        int ch = idx >> 8;
        int rowp = idx & 255;
        int ii = rowp & 15, g = rowp >> 4;
        const float* bsrc;
        int srow;
        if (ch >= 3) { bsrc = b311; srow = ii * 48 + (ch - 3) * 16 + g; }
        else {
            bsrc = (ch == 0) ? b300 : (ch == 1) ? b301 : b310;
            srow = ii * 16 + g;
        }
        b3a[idx] = bsrc[srow];
    }

    // ---- prologue: warp w -> node (w&15), m in {mh*2, mh*2+1} ----
    const int pnode = w & 15;
    const int mh    = w >> 4;
    const int node  = blk * CK_NODES + pnode;
    const int eb    = node * EDIM;          // first edge of node
    const float x   = r[eb];
    const int k     = lane;

    #pragma unroll
    for (int mi = 0; mi < 2; mi++) {
        const int m = mh * 2 + mi;
        // layer1 + LN + relu
        float v = fmaf(x, w1[m * 32 + k], b1[m * 32 + k]);
        float mu = warp_sum(v) * (1.f / 32.f);
        float d = v - mu;
        float var = warp_sum(d * d) * (1.f / 32.f);
        v = fmaf(d * rsqrtf(var + 1e-5f), g1[m * 32 + k], be1[m * 32 + k]);
        v = fmaxf(v, 0.f);
        // layer2: per-lane w2 row in registers (L2-resident), shuffle-broadcast dot
        float w2reg[32];
        const float4* w2r = (const float4*)(w2 + (m * 32 + k) * 32);
        #pragma unroll
        for (int q = 0; q < 8; q++) {
            float4 tmp = w2r[q];
            w2reg[q * 4 + 0] = tmp.x; w2reg[q * 4 + 1] = tmp.y;
            w2reg[q * 4 + 2] = tmp.z; w2reg[q * 4 + 3] = tmp.w;
        }
        float acc = b2[m * 32 + k];
        #pragma unroll
        for (int kk = 0; kk < 32; kk++)
            acc = fmaf(__shfl_sync(0xffffffffu, v, kk), w2reg[kk], acc);
        float mu2 = warp_sum(acc) * (1.f / 32.f);
        float d2 = acc - mu2;
        float var2 = warp_sum(d2 * d2) * (1.f / 32.f);
        acc = fmaf(d2 * rsqrtf(var2 + 1e-5f), g2[m * 32 + k], be2[m * 32 + k]);
        acc = fmaxf(acc, 0.f);
        h2s[(pnode * 4 + m) * 32 + k] = acc;
    }

    // ---- per-node aux (warps 0..15, lanes < 16) ----
    if (w < 16 && lane < 16) {
        const int j = lane;
        float s0v = src0[eb * 16 + j];
        float s1a = src1[eb * 48 + j * 3 + 0];
        float s1b = src1[eb * 48 + j * 3 + 1];
        float s1c = src1[eb * 48 + j * 3 + 2];
        s0s[w * 16 + j]  = s0v;
        c00s[w * 16 + j] = b00g[node] * s0v;
        ws1s[w * 16 + j] = b10g[node * 3 + 0] * s1a
                         + b10g[node * 3 + 1] * s1b
                         + b10g[node * 3 + 2] * s1c;
        #pragma unroll
        for (int a = 0; a < 3; a++) {
            #pragma unroll
            for (int f = 0; f < 3; f++) {
                v11s[(w * 3 + a) * 48 + j * 3 + f] =
                      b11g[node * 27 + a * 9 + 0 * 3 + f] * s1a
                    + b11g[node * 27 + a * 9 + 1 * 3 + f] * s1b
                    + b11g[node * 27 + a * 9 + 2 * 3 + f] * s1c;
            }
        }
        if (j < 3) b01sm[w * 3 + j] = b01g[node * 3 + j];
    }
    __syncthreads();   // barrier #1

    // ---- main GEMM + fused contraction ----
    // warp w: node pair pA=(w&7)*2, pB=pA+1; quarter = w>>3 -> rows [q*64, q*64+64)
    const int pA = (w & 7) * 2;
    const int pB = pA + 1;
    const int quarter = w >> 3;
    const int li = lane & 15;
    const int hi = lane >> 4;

    const int rowp0 = quarter * 64 + lane;
    const int rowp1 = rowp0 + 32;
    const int sw    = rowp0 & 7;          // same for rowp1
    const int g0    = quarter * 4 + hi;   // rowp0 >> 4
    const int g1i   = g0 + 2;             // rowp1 >> 4

    const float bA0 = b01sm[pA * 3 + 0], bA1 = b01sm[pA * 3 + 1], bA2 = b01sm[pA * 3 + 2];
    const float bB0 = b01sm[pB * 3 + 0], bB1 = b01sm[pB * 3 + 1], bB2 = b01sm[pB * 3 + 2];

    float a0A = 0.f, a0B = 0.f;
    float a1A0 = 0.f, a1A1 = 0.f, a1A2 = 0.f;
    float a1B0 = 0.f, a1B1 = 0.f, a1B2 = 0.f;

    #pragma unroll
    for (int ch = 0; ch < 6; ch++) {
        const int m = (ch < 3) ? ch : 3;
        const int cc = (ch >= 3) ? (ch - 3) : 0;

        const float4* ha = (const float4*)&h2s[(pA * 4 + m) * 32];
        const float4* hb = (const float4*)&h2s[(pB * 4 + m) * 32];
        const float4* wr0 = (const float4*)Wall + ch * 2048 + rowp0 * 8;
        const float4* wr1 = (const float4*)Wall + ch * 2048 + rowp1 * 8;
        const float*  bch = b3a + ch * 256;

        float vA0 = bch[rowp0], vB0 = vA0;
        float vA1 = bch[rowp1], vB1 = vA1;
        #pragma unroll
        for (int q = 0; q < 8; q++) {
            float4 hA = ha[q];
            float4 hB = hb[q];
            float4 w0 = wr0[q ^ sw];
            float4 w1v = wr1[q ^ sw];
            DOT4(vA0, hA, w0);
            DOT4(vB0, hB, w0);
            DOT4(vA1, hA, w1v);
            DOT4(vB1, hB, w1v);
        }

        #pragma unroll
        for (int rr = 0; rr < 2; rr++) {
            const float vA = (rr == 0) ? vA0 : vA1;
            const float vB = (rr == 0) ? vB0 : vB1;
            const int g = (rr == 0) ? g0 : g1i;

            if (ch == 0) {
                a0A = fmaf(vA, c00s[pA * 16 + g], a0A);
                a0B = fmaf(vB, c00s[pB * 16 + g], a0B);
            } else if (ch == 1) {
                float tA = vA * s0s[pA * 16 + g];
                float tB = vB * s0s[pB * 16 + g];
                a1A0 = fmaf(tA, bA0, a1A0); a1A1 = fmaf(tA, bA1, a1A1); a1A2 = fmaf(tA, bA2, a1A2);
                a1B0 = fmaf(tB, bB0, a1B0); a1B1 = fmaf(tB, bB1, a1B1); a1B2 = fmaf(tB, bB2, a1B2);
            } else if (ch == 2) {
                a0A = fmaf(vA, ws1s[pA * 16 + g], a0A);
                a0B = fmaf(vB, ws1s[pB * 16 + g], a0B);
            } else {
                const int gg = cc * 16 + g;
                a1A0 = fmaf(vA, v11s[(pA * 3 + 0) * 48 + gg], a1A0);
                a1A1 = fmaf(vA, v11s[(pA * 3 + 1) * 48 + gg], a1A1);
                a1A2 = fmaf(vA, v11s[(pA * 3 + 2) * 48 + gg], a1A2);
                a1B0 = fmaf(vB, v11s[(pB * 3 + 0) * 48 + gg], a1B0);
                a1B1 = fmaf(vB, v11s[(pB * 3 + 1) * 48 + gg], a1B1);
                a1B2 = fmaf(vB, v11s[(pB * 3 + 2) * 48 + gg], a1B2);
            }
        }
    }

    // ---- reduce lane pairs (xor 16), accumulate node messages in smem ----
    a0A  += __shfl_xor_sync(0xffffffffu, a0A, 16);
    a0B  += __shfl_xor_sync(0xffffffffu, a0B, 16);
    a1A0 += __shfl_xor_sync(0xffffffffu, a1A0, 16);
    a1A1 += __shfl_xor_sync(0xffffffffu, a1A1, 16);
    a1A2 += __shfl_xor_sync(0xffffffffu, a1A2, 16);
    a1B0 += __shfl_xor_sync(0xffffffffu, a1B0, 16);
    a1B1 += __shfl_xor_sync(0xffffffffu, a1B1, 16);
    a1B2 += __shfl_xor_sync(0xffffffffu, a1B2, 16);

    if (lane < 16) {
        atomicAdd(&msgAcc[pA * 64 + li], a0A);
        atomicAdd(&msgAcc[pB * 64 + li], a0B);
        atomicAdd(&msgAcc[pA * 64 + 16 + li * 3 + 0], a1A0);
        atomicAdd(&msgAcc[pA * 64 + 16 + li * 3 + 1], a1A1);
        atomicAdd(&msgAcc[pA * 64 + 16 + li * 3 + 2], a1A2);
        atomicAdd(&msgAcc[pB * 64 + 16 + li * 3 + 0], a1B0);
        atomicAdd(&msgAcc[pB * 64 + 16 + li * 3 + 1], a1B1);
        atomicAdd(&msgAcc[pB * 64 + 16 + li * 3 + 2], a1B2);
    }
    __syncthreads();   // barrier #2

    // ---- fused broadcast: stream this block's 16 nodes to all 127 edges ----
    const float4* mq = (const float4*)msgAcc;
    const int bn0 = blk * CK_NODES;

    // out0: per node 508 float4 (period 4); iterate virtual period 512
    #pragma unroll
    for (int rep = 0; rep < 8; rep++) {
        int idx = rep * CK_THREADS + t;
        int nn = idx >> 9;
        int e4 = idx & 511;
        if (e4 < 508)
            out[(size_t)(bn0 + nn) * 508 + e4] = mq[nn * 16 + (e4 & 3)];
    }

    // out1: per node 1524 float4 (period 12); 2 strided stores per thread
    const int t12a = t % 12;
    const int t12b = (t12a + 4) % 12;        // (t + 1024) % 12
    const int j2 = t + CK_THREADS;
    #pragma unroll 1
    for (int nn = 0; nn < CK_NODES; nn++) {
        const float4* mrow = mq + nn * 16;   // [0..3]=msg0, [4..15]=msg1
        float4* o1 = out + OUT1_BASE4 + (size_t)(bn0 + nn) * 1524;
        float4 va = mrow[4 + t12a];
        o1[t] = va;
        if (j2 < 1524) o1[j2] = mrow[4 + t12b];
    }
}

extern "C" void kernel_launch(void* const* d_in, const int* in_sizes, int n_in,
                              void* d_out, int out_size)
{
    const float* r    = (const float*)d_in[0];
    const float* src0 = (const float*)d_in[1];
    const float* src1 = (const float*)d_in[2];
    const float* b00  = (const float*)d_in[3];
    const float* b01  = (const float*)d_in[4];
    const float* b10  = (const float*)d_in[5];
    const float* b11  = (const float*)d_in[6];
    const float* w1   = (const float*)d_in[7];
    const float* b1   = (const float*)d_in[8];
    const float* g1   = (const float*)d_in[9];
    const float* be1  = (const float*)d_in[10];
    const float* w2   = (const float*)d_in[11];
    const float* b2   = (const float*)d_in[12];
    const float* g2   = (const float*)d_in[13];
    const float* be2  = (const float*)d_in[14];
    const float* w300 = (const float*)d_in[15];
    const float* b300 = (const float*)d_in[16];
    const float* w301 = (const float*)d_in[17];
    const float* b301 = (const float*)d_in[18];
    const float* w310 = (const float*)d_in[19];
    const float* b310 = (const float*)d_in[20];
    const float* w311 = (const float*)d_in[21];
    const float* b311 = (const float*)d_in[22];

    static int smem_set = 0;
    if (!smem_set) {
        cudaFuncSetAttribute(fused_kernel,
                             cudaFuncAttributeMaxDynamicSharedMemorySize, SMEM_BYTES);
        smem_set = 1;
    }

    fused_kernel<<<CK_BLOCKS, CK_THREADS, SMEM_BYTES>>>(
        r, src0, src1, b00, b01, b10, b11,
        w1, b1, g1, be1, w2, b2, g2, be2,
        w300, b300, w301, b301, w310, b310, w311, b311,
        (float4*)d_out);
}

// round 7
// speedup vs baseline: 1.1321x; 1.1321x over previous
#include <cuda_runtime.h>
#include <cstdint>

// Problem constants
#define EDIM   127
#define BN     2048                 // B*N
#define BNE    260096               // B*N*E

#define CT        512
#define NODES     16
#define GROUPS    128               // BN / NODES

// Smem layout (floats), identical for both halves. Total 28672 floats = 114688 B
// -> two blocks per SM (229376 + reserve <= 233472).
#define OFF_W    0                  // 3 slots * 256 rows * 32 = 24576 (XOR-swizzled)
#define OFF_B3   24576              // 3 * 256 = 768 (permuted g*16+i)
#define OFF_H2   25344              // 16 nodes * 3 mslots * 32 = 1536 (aliased by msgAcc)
#define OFF_AUX  26880              // 1792
#define SMF      28672
#define SMB      (SMF * 4)          // 114688

// A-half aux sublayout: s0 @0 (256), b00 @256 (16), b01 @272 (48), v11a @320 (768)
// B-half aux sublayout: ws1 @0 (256), v11b @256 (1536)

#define OUT1_BASE4 1040384          // (BNE*16)/4

// Per-(half, node) partial messages: slot written exactly once per launch
__device__ float g_part[2 * BN * 64];

__device__ __forceinline__ float warp_sum(float v) {
    v += __shfl_xor_sync(0xffffffffu, v, 16);
    v += __shfl_xor_sync(0xffffffffu, v, 8);
    v += __shfl_xor_sync(0xffffffffu, v, 4);
    v += __shfl_xor_sync(0xffffffffu, v, 2);
    v += __shfl_xor_sync(0xffffffffu, v, 1);
    return v;
}

#define DOT4(acc, h, wv) do { \
    acc = fmaf((h).x, (wv).x, acc); \
    acc = fmaf((h).y, (wv).y, acc); \
    acc = fmaf((h).z, (wv).z, acc); \
    acc = fmaf((h).w, (wv).w, acc); } while (0)

extern "C" __global__ void __launch_bounds__(CT, 2)
compute_kernel(const float* __restrict__ r,
               const float* __restrict__ src0,
               const float* __restrict__ src1,
               const float* __restrict__ b00g,
               const float* __restrict__ b01g,
               const float* __restrict__ b10g,
               const float* __restrict__ b11g,
               const float* __restrict__ w1,
               const float* __restrict__ b1,
               const float* __restrict__ g1,
               const float* __restrict__ be1,
               const float* __restrict__ w2,
               const float* __restrict__ b2,
               const float* __restrict__ g2,
               const float* __restrict__ be2,
               const float* __restrict__ w300, const float* __restrict__ b300,
               const float* __restrict__ w301, const float* __restrict__ b301,
               const float* __restrict__ w310, const float* __restrict__ b310,
               const float* __restrict__ w311, const float* __restrict__ b311)
{
    extern __shared__ float sm[];
    float*  Wsm  = sm + OFF_W;
    float4* Wsm4 = (float4*)Wsm;
    float*  b3s  = sm + OFF_B3;
    float*  h2s  = sm + OFF_H2;
    float*  aux  = sm + OFF_AUX;

    const int t    = threadIdx.x;
    const int lane = t & 31;
    const int w    = t >> 5;            // 0..15, = node-in-block for prologue
    const int blk  = blockIdx.x;
    const int hB   = blockIdx.y;        // 0 = half A, 1 = half B

    // ---- stage 3 W3 slices (permuted srowp = g*16+i, XOR-swizzled) ----
    for (int d4 = t; d4 < 6144; d4 += CT) {
        int slot = d4 >> 11, rem = d4 & 2047;
        int rowp = rem >> 3, k4 = rem & 7;
        int i = rowp & 15, g = rowp >> 4;
        const float4* src; int srow;
        if (!hB) {
            if (slot == 0)      { src = (const float4*)w300; srow = i * 16 + g; }
            else if (slot == 1) { src = (const float4*)w301; srow = i * 16 + g; }
            else                { src = (const float4*)w311; srow = i * 48 + g; }
        } else {
            if (slot == 0)      { src = (const float4*)w310; srow = i * 16 + g; }
            else if (slot == 1) { src = (const float4*)w311; srow = i * 48 + 16 + g; }
            else                { src = (const float4*)w311; srow = i * 48 + 32 + g; }
        }
        Wsm4[slot * 2048 + rowp * 8 + (k4 ^ (rowp & 7))] = src[srow * 8 + k4];
    }
    // ---- stage biases (same permutation) ----
    for (int idx = t; idx < 768; idx += CT) {
        int slot = idx >> 8, rowp = idx & 255;
        int i = rowp & 15, g = rowp >> 4;
        const float* bs; int srow;
        if (!hB) {
            if (slot == 0)      { bs = b300; srow = i * 16 + g; }
            else if (slot == 1) { bs = b301; srow = i * 16 + g; }
            else                { bs = b311; srow = i * 48 + g; }
        } else {
            if (slot == 0)      { bs = b310; srow = i * 16 + g; }
            else if (slot == 1) { bs = b311; srow = i * 48 + 16 + g; }
            else                { bs = b311; srow = i * 48 + 32 + g; }
        }
        b3s[idx] = bs[srow];
    }

    // ---- prologue: warp w computes its half's MLPs for node blk*16+w ----
    const int node = blk * NODES + w;
    const int eb   = node * EDIM;
    const float x  = r[eb];
    const int k    = lane;
    const int nm   = hB ? 2 : 3;

    for (int mi = 0; mi < nm; mi++) {
        const int m = hB ? (mi + 2) : (mi == 2 ? 3 : mi);
        // layer1 + LN + relu
        float v = fmaf(x, w1[m * 32 + k], b1[m * 32 + k]);
        float mu = warp_sum(v) * (1.f / 32.f);
        float d = v - mu;
        float var = warp_sum(d * d) * (1.f / 32.f);
        v = fmaf(d * rsqrtf(var + 1e-5f), g1[m * 32 + k], be1[m * 32 + k]);
        v = fmaxf(v, 0.f);
        // layer2: per-lane w2 row from L2, shuffle-broadcast dot
        float w2reg[32];
        const float4* w2r = (const float4*)(w2 + (m * 32 + k) * 32);
        #pragma unroll
        for (int q = 0; q < 8; q++) {
            float4 tmp = w2r[q];
            w2reg[q * 4 + 0] = tmp.x; w2reg[q * 4 + 1] = tmp.y;
            w2reg[q * 4 + 2] = tmp.z; w2reg[q * 4 + 3] = tmp.w;
        }
        float acc = b2[m * 32 + k];
        #pragma unroll
        for (int kk = 0; kk < 32; kk++)
            acc = fmaf(__shfl_sync(0xffffffffu, v, kk), w2reg[kk], acc);
        float mu2 = warp_sum(acc) * (1.f / 32.f);
        float d2 = acc - mu2;
        float var2 = warp_sum(d2 * d2) * (1.f / 32.f);
        acc = fmaf(d2 * rsqrtf(var2 + 1e-5f), g2[m * 32 + k], be2[m * 32 + k]);
        acc = fmaxf(acc, 0.f);
        h2s[(w * 3 + mi) * 32 + k] = acc;
    }

    // ---- per-node aux (lanes < 16) ----
    if (lane < 16) {
        const int j = lane;
        if (!hB) {
            float s0v = src0[eb * 16 + j];
            aux[w * 16 + j] = s0v;                       // s0
            if (j == 0) aux[256 + w] = b00g[node];       // b00
            if (j < 3)  aux[272 + w * 3 + j] = b01g[node * 3 + j];
            int jj = j / 3, f = j - jj * 3;              // q = j (ch3, cc=0)
            float sa = src1[eb * 48 + jj * 3 + 0];
            float sb = src1[eb * 48 + jj * 3 + 1];
            float sc = src1[eb * 48 + jj * 3 + 2];
            #pragma unroll
            for (int a = 0; a < 3; a++) {
                aux[320 + (w * 3 + a) * 16 + j] =
                      b11g[node * 27 + a * 9 + 0 + f] * sa
                    + b11g[node * 27 + a * 9 + 3 + f] * sb
                    + b11g[node * 27 + a * 9 + 6 + f] * sc;
            }
        } else {
            float sa = src1[eb * 48 + j * 3 + 0];
            float sb = src1[eb * 48 + j * 3 + 1];
            float sc = src1[eb * 48 + j * 3 + 2];
            aux[w * 16 + j] = b10g[node * 3 + 0] * sa    // ws1
                            + b10g[node * 3 + 1] * sb
                            + b10g[node * 3 + 2] * sc;
            // ch4: q = 16+j
            {
                int q = 16 + j, jj = q / 3, f = q - jj * 3;
                float ta = src1[eb * 48 + jj * 3 + 0];
                float tb = src1[eb * 48 + jj * 3 + 1];
                float tc = src1[eb * 48 + jj * 3 + 2];
                #pragma unroll
                for (int a = 0; a < 3; a++)
                    aux[256 + (w * 3 + a) * 32 + j] =
                          b11g[node * 27 + a * 9 + 0 + f] * ta
                        + b11g[node * 27 + a * 9 + 3 + f] * tb
                        + b11g[node * 27 + a * 9 + 6 + f] * tc;
            }
            // ch5: q = 32+j
            {
                int q = 32 + j, jj = q / 3, f = q - jj * 3;
                float ua = src1[eb * 48 + jj * 3 + 0];
                float ub = src1[eb * 48 + jj * 3 + 1];
                float uc = src1[eb * 48 + jj * 3 + 2];
                #pragma unroll
                for (int a = 0; a < 3; a++)
                    aux[256 + (w * 3 + a) * 32 + 16 + j] =
                          b11g[node * 27 + a * 9 + 0 + f] * ua
                        + b11g[node * 27 + a * 9 + 3 + f] * ub
                        + b11g[node * 27 + a * 9 + 6 + f] * uc;
            }
        }
    }
    __syncthreads();   // weights + h2 + aux ready

    // ---- main loop: warp = (node-pair, g-half); K split across lane pairs ----
    const int pA = (w & 7) * 2;
    const int pB = pA + 1;
    const int ghalf = w >> 3;
    const int li = lane & 15;
    const int khalf = lane >> 4;
    const int c0 = (khalf * 4 + 0) ^ (li & 7);
    const int c1 = (khalf * 4 + 1) ^ (li & 7);
    const int c2 = (khalf * 4 + 2) ^ (li & 7);
    const int c3 = (khalf * 4 + 3) ^ (li & 7);
    const int rbase = ghalf * 128 + li;     // srowp at iter 0 (step 16)

    float z0A = 0.f, z0B = 0.f;                 // ch0 / ch2
    float z1A = 0.f, z1B = 0.f;                 // ch1 (A only)
    float xA0 = 0.f, xA1 = 0.f, xA2 = 0.f;      // ch4 (B)
    float xB0 = 0.f, xB1 = 0.f, xB2 = 0.f;
    float yA0 = 0.f, yA1 = 0.f, yA2 = 0.f;      // ch3 (A) / ch5 (B)
    float yB0 = 0.f, yB1 = 0.f, yB2 = 0.f;

#define LOAD_H(slot) \
    { const float4* hp = (const float4*)&h2s[(pA * 3 + (slot)) * 32] + khalf * 4; \
      hA0 = hp[0]; hA1 = hp[1]; hA2 = hp[2]; hA3 = hp[3]; \
      const float4* hq = (const float4*)&h2s[(pB * 3 + (slot)) * 32] + khalf * 4; \
      hB0 = hq[0]; hB1 = hq[1]; hB2 = hq[2]; hB3 = hq[3]; }

#define ROW_DOT(slot, it, vA, vB) \
    float vA, vB; \
    { float bb = b3s[(slot) * 256 + rbase + (it) * 16]; \
      float aA = khalf ? 0.f : bb; float aB = aA; \
      const float4* wr = Wsm4 + (slot) * 2048 + (rbase + (it) * 16) * 8; \
      float4 w0 = wr[c0], w1v = wr[c1], w2v = wr[c2], w3v = wr[c3]; \
      DOT4(aA, hA0, w0); DOT4(aA, hA1, w1v); DOT4(aA, hA2, w2v); DOT4(aA, hA3, w3v); \
      DOT4(aB, hB0, w0); DOT4(aB, hB1, w1v); DOT4(aB, hB2, w2v); DOT4(aB, hB3, w3v); \
      aA += __shfl_xor_sync(0xffffffffu, aA, 16); \
      aB += __shfl_xor_sync(0xffffffffu, aB, 16); \
      vA = aA; vB = aB; }

    float4 hA0, hA1, hA2, hA3, hB0, hB1, hB2, hB3;

    if (!hB) {
        // ch0 (slot0, m-slot0): z0 += v * s0[g]
        LOAD_H(0);
        #pragma unroll
        for (int it = 0; it < 8; it++) {
            ROW_DOT(0, it, vA, vB);
            int g = ghalf * 8 + it;
            z0A = fmaf(vA, aux[pA * 16 + g], z0A);
            z0B = fmaf(vB, aux[pB * 16 + g], z0B);
        }
        // ch1 (slot1, m-slot1): z1 += v * s0[g]
        LOAD_H(1);
        #pragma unroll
        for (int it = 0; it < 8; it++) {
            ROW_DOT(1, it, vA, vB);
            int g = ghalf * 8 + it;
            z1A = fmaf(vA, aux[pA * 16 + g], z1A);
            z1B = fmaf(vB, aux[pB * 16 + g], z1B);
        }
        // ch3 (slot2, m-slot2): y[a] += v * v11a[a][g]
        LOAD_H(2);
        #pragma unroll
        for (int it = 0; it < 8; it++) {
            ROW_DOT(2, it, vA, vB);
            int g = ghalf * 8 + it;
            yA0 = fmaf(vA, aux[320 + (pA * 3 + 0) * 16 + g], yA0);
            yA1 = fmaf(vA, aux[320 + (pA * 3 + 1) * 16 + g], yA1);
            yA2 = fmaf(vA, aux[320 + (pA * 3 + 2) * 16 + g], yA2);
            yB0 = fmaf(vB, aux[320 + (pB * 3 + 0) * 16 + g], yB0);
            yB1 = fmaf(vB, aux[320 + (pB * 3 + 1) * 16 + g], yB1);
            yB2 = fmaf(vB, aux[320 + (pB * 3 + 2) * 16 + g], yB2);
        }
    } else {
        // ch2 (slot0, m-slot0): z0 += v * ws1[g]
        LOAD_H(0);
        #pragma unroll
        for (int it = 0; it < 8; it++) {
            ROW_DOT(0, it, vA, vB);
            int g = ghalf * 8 + it;
            z0A = fmaf(vA, aux[pA * 16 + g], z0A);
            z0B = fmaf(vB, aux[pB * 16 + g], z0B);
        }
        // ch4 (slot1, m-slot1): x[a] += v * v11b[a][g]
        LOAD_H(1);
        #pragma unroll
        for (int it = 0; it < 8; it++) {
            ROW_DOT(1, it, vA, vB);
            int g = ghalf * 8 + it;
            xA0 = fmaf(vA, aux[256 + (pA * 3 + 0) * 32 + g], xA0);
            xA1 = fmaf(vA, aux[256 + (pA * 3 + 1) * 32 + g], xA1);
            xA2 = fmaf(vA, aux[256 + (pA * 3 + 2) * 32 + g], xA2);
            xB0 = fmaf(vB, aux[256 + (pB * 3 + 0) * 32 + g], xB0);
            xB1 = fmaf(vB, aux[256 + (pB * 3 + 1) * 32 + g], xB1);
            xB2 = fmaf(vB, aux[256 + (pB * 3 + 2) * 32 + g], xB2);
        }
        // ch5 (slot2, same m-slot1 h): y[a] += v * v11b[a][16+g]
        #pragma unroll
        for (int it = 0; it < 8; it++) {
            ROW_DOT(2, it, vA, vB);
            int g = ghalf * 8 + it;
            yA0 = fmaf(vA, aux[256 + (pA * 3 + 0) * 32 + 16 + g], yA0);
            yA1 = fmaf(vA, aux[256 + (pA * 3 + 1) * 32 + 16 + g], yA1);
            yA2 = fmaf(vA, aux[256 + (pA * 3 + 2) * 32 + 16 + g], yA2);
            yB0 = fmaf(vB, aux[256 + (pB * 3 + 0) * 32 + 16 + g], yB0);
            yB1 = fmaf(vB, aux[256 + (pB * 3 + 1) * 32 + 16 + g], yB1);
            yB2 = fmaf(vB, aux[256 + (pB * 3 + 2) * 32 + 16 + g], yB2);
        }
    }

    // ---- reuse h2 region as per-node message accumulator ----
    __syncthreads();                       // all h2 reads done
    float* msgAcc = h2s;                   // 1024 floats: [node][64]
    for (int idx = t; idx < 1024; idx += CT) msgAcc[idx] = 0.f;
    __syncthreads();

    if (lane < 16) {
        if (!hB) {
            float b00A = aux[256 + pA], b00B = aux[256 + pB];
            float bA0 = aux[272 + pA * 3 + 0], bA1 = aux[272 + pA * 3 + 1], bA2 = aux[272 + pA * 3 + 2];
            float bB0 = aux[272 + pB * 3 + 0], bB1 = aux[272 + pB * 3 + 1], bB2 = aux[272 + pB * 3 + 2];
            atomicAdd(&msgAcc[pA * 64 + li], z0A * b00A);
            atomicAdd(&msgAcc[pB * 64 + li], z0B * b00B);
            atomicAdd(&msgAcc[pA * 64 + 16 + li * 3 + 0], fmaf(z1A, bA0, yA0));
            atomicAdd(&msgAcc[pA * 64 + 16 + li * 3 + 1], fmaf(z1A, bA1, yA1));
            atomicAdd(&msgAcc[pA * 64 + 16 + li * 3 + 2], fmaf(z1A, bA2, yA2));
            atomicAdd(&msgAcc[pB * 64 + 16 + li * 3 + 0], fmaf(z1B, bB0, yB0));
            atomicAdd(&msgAcc[pB * 64 + 16 + li * 3 + 1], fmaf(z1B, bB1, yB1));
            atomicAdd(&msgAcc[pB * 64 + 16 + li * 3 + 2], fmaf(z1B, bB2, yB2));
        } else {
            atomicAdd(&msgAcc[pA * 64 + li], z0A);
            atomicAdd(&msgAcc[pB * 64 + li], z0B);
            atomicAdd(&msgAcc[pA * 64 + 16 + li * 3 + 0], xA0 + yA0);
            atomicAdd(&msgAcc[pA * 64 + 16 + li * 3 + 1], xA1 + yA1);
            atomicAdd(&msgAcc[pA * 64 + 16 + li * 3 + 2], xA2 + yA2);
            atomicAdd(&msgAcc[pB * 64 + 16 + li * 3 + 0], xB0 + yB0);
            atomicAdd(&msgAcc[pB * 64 + 16 + li * 3 + 1], xB1 + yB1);
            atomicAdd(&msgAcc[pB * 64 + 16 + li * 3 + 2], xB2 + yB2);
        }
    }
    __syncthreads();

    // ---- write this half's partial messages ----
    float* dst = g_part + hB * (BN * 64) + blk * 1024;
    for (int idx = t; idx < 1024; idx += CT) dst[idx] = msgAcc[idx];
}

// ---- broadcast: sum 2 partials per node, fan out to 127 edges ----
extern "C" __global__ void __launch_bounds__(256)
broadcast_kernel(float4* __restrict__ out)
{
    const int bn = blockIdx.x;
    const int t  = threadIdx.x;
    __shared__ float4 m0q[4];
    __shared__ float4 m1q[12];

    if (t < 16) {
        const float4* a = (const float4*)(g_part + bn * 64);
        const float4* b = (const float4*)(g_part + BN * 64 + bn * 64);
        float4 xa = a[t], xb = b[t];
        float4 s = make_float4(xa.x + xb.x, xa.y + xb.y, xa.z + xb.z, xa.w + xb.w);
        if (t < 4) m0q[t] = s; else m1q[t - 4] = s;
    }
    __syncthreads();

    // out0: 508 float4, period 4 (256 % 4 == 0 -> column constant)
    float4* o0 = out + (size_t)bn * 508;
    float4 v0 = m0q[t & 3];
    o0[t] = v0;
    if (t < 252) o0[t + 256] = v0;

    // out1: 1524 float4, period 12; div-free periodic index (256 % 12 == 4)
    float4* o1 = out + OUT1_BASE4 + (size_t)bn * 1524;
    int s12 = t % 12;
    int idx = t;
    #pragma unroll
    for (int itr = 0; itr < 6; itr++) {
        if (idx < 1524) o1[idx] = m1q[s12];
        idx += 256;
        s12 += 4; if (s12 >= 12) s12 -= 12;
    }
}

extern "C" void kernel_launch(void* const* d_in, const int* in_sizes, int n_in,
                              void* d_out, int out_size)
{
    const float* r    = (const float*)d_in[0];
    const float* src0 = (const float*)d_in[1];
    const float* src1 = (const float*)d_in[2];
    const float* b00  = (const float*)d_in[3];
    const float* b01  = (const float*)d_in[4];
    const float* b10  = (const float*)d_in[5];
    const float* b11  = (const float*)d_in[6];
    const float* w1   = (const float*)d_in[7];
    const float* b1   = (const float*)d_in[8];
    const float* g1   = (const float*)d_in[9];
    const float* be1  = (const float*)d_in[10];
    const float* w2   = (const float*)d_in[11];
    const float* b2   = (const float*)d_in[12];
    const float* g2   = (const float*)d_in[13];
    const float* be2  = (const float*)d_in[14];
    const float* w300 = (const float*)d_in[15];
    const float* b300 = (const float*)d_in[16];
    const float* w301 = (const float*)d_in[17];
    const float* b301 = (const float*)d_in[18];
    const float* w310 = (const float*)d_in[19];
    const float* b310 = (const float*)d_in[20];
    const float* w311 = (const float*)d_in[21];
    const float* b311 = (const float*)d_in[22];

    cudaFuncSetAttribute(compute_kernel,
                         cudaFuncAttributeMaxDynamicSharedMemorySize, SMB);

    compute_kernel<<<dim3(GROUPS, 2), CT, SMB>>>(
        r, src0, src1, b00, b01, b10, b11,
        w1, b1, g1, be1, w2, b2, g2, be2,
        w300, b300, w301, b301, w310, b310, w311, b311);

    broadcast_kernel<<<BN, 256>>>((float4*)d_out);
}

// round 8
// speedup vs baseline: 1.3087x; 1.1560x over previous
#include <cuda_runtime.h>
#include <cstdint>

// Problem constants
#define EDIM   127
#define BN     2048                 // B*N
#define BNE    260096               // B*N*E

#define CT      512
#define NODES   16
#define GROUPS  128                 // BN / NODES

// Smem layout (floats). Total 56976 floats = 227904 B (<= 232448 opt-in).
#define OFF_W     0                 // 6 slots * 256 rows * 32 = 49152
#define OFF_B3    49152             // 6 * 256 = 1536
#define OFF_H2    50688             // 16 nodes * 132 = 2112 (pad for banks)
#define OFF_AUXA  52800             // 16 * 65 = 1040  (c00|s0|ws1|b01)
#define OFF_V11   53840             // 16 * 49 float4 = 3136 floats
#define SMF       56976
#define SMB       (SMF * 4)

#define H2PAD  132
#define AXPAD  65
#define V11PAD 49

#define OUT1_BASE4 1040384          // (BNE*16)/4

// Final per-node messages: [BN][64] = msg0[16] | msg1[48]; every slot written once
__device__ float g_msg[BN * 64];

__device__ __forceinline__ float warp_sum(float v) {
    v += __shfl_xor_sync(0xffffffffu, v, 16);
    v += __shfl_xor_sync(0xffffffffu, v, 8);
    v += __shfl_xor_sync(0xffffffffu, v, 4);
    v += __shfl_xor_sync(0xffffffffu, v, 2);
    v += __shfl_xor_sync(0xffffffffu, v, 1);
    return v;
}

// packed fp32x2 FMA: d = a*b + d (elementwise on 2 packed floats)
__device__ __forceinline__ void ffma2(unsigned long long& d,
                                      unsigned long long a,
                                      unsigned long long b) {
    asm("fma.rn.f32x2 %0, %1, %2, %0;" : "+l"(d) : "l"(a), "l"(b));
}

extern "C" __global__ void __launch_bounds__(CT, 1)
compute_kernel(const float* __restrict__ r,
               const float* __restrict__ src0,
               const float* __restrict__ src1,
               const float* __restrict__ b00g,
               const float* __restrict__ b01g,
               const float* __restrict__ b10g,
               const float* __restrict__ b11g,
               const float* __restrict__ w1,
               const float* __restrict__ b1,
               const float* __restrict__ g1,
               const float* __restrict__ be1,
               const float* __restrict__ w2,
               const float* __restrict__ b2,
               const float* __restrict__ g2,
               const float* __restrict__ be2,
               const float* __restrict__ w300, const float* __restrict__ b300,
               const float* __restrict__ w301, const float* __restrict__ b301,
               const float* __restrict__ w310, const float* __restrict__ b310,
               const float* __restrict__ w311, const float* __restrict__ b311)
{
    extern __shared__ float sm[];
    float* Wsm = sm + OFF_W;     // [slot][rowq = i*16+gq][32]
    float* b3s = sm + OFF_B3;    // [slot][rowq]
    float* h2s = sm + OFF_H2;    // [node*H2PAD + m*32 + k]
    float* axA = sm + OFF_AUXA;  // [node*AXPAD + {0:c00,16:s0,32:ws1,48:b01}]
    float4* v4 = (float4*)(sm + OFF_V11);  // [node*V11PAD + X], a in xyz

    const int t    = threadIdx.x;
    const int lane = t & 31;
    const int w    = t >> 5;           // warp id (= node in prologue, = i in main)
    const int blk  = blockIdx.x;

    // ---- stage 6 weight slots: dest row rowq = i*16+gq, k-contiguous ----
    float4* Wsm4 = (float4*)Wsm;
    for (int d4 = t; d4 < 12288; d4 += CT) {
        int slot = d4 >> 11, rem = d4 & 2047;
        int rowq = rem >> 3, k4 = rem & 7;
        const float4* src; int srow;
        if (slot == 0)      { src = (const float4*)w300; srow = rowq; }
        else if (slot == 1) { src = (const float4*)w301; srow = rowq; }
        else if (slot == 2) { src = (const float4*)w310; srow = rowq; }
        else {
            src = (const float4*)w311;
            srow = (rowq >> 4) * 48 + (slot - 3) * 16 + (rowq & 15);
        }
        Wsm4[slot * 2048 + rowq * 8 + k4] = src[srow * 8 + k4];
    }
    for (int idx = t; idx < 1536; idx += CT) {
        int slot = idx >> 8, rowq = idx & 255;
        const float* bs; int srow;
        if (slot == 0)      { bs = b300; srow = rowq; }
        else if (slot == 1) { bs = b301; srow = rowq; }
        else if (slot == 2) { bs = b310; srow = rowq; }
        else { bs = b311; srow = (rowq >> 4) * 48 + (slot - 3) * 16 + (rowq & 15); }
        b3s[idx] = bs[srow];
    }

    // ---- prologue: warp w = node, computes 4 MLPs + aux ----
    const int node0 = blk * NODES + w;
    const int eb    = node0 * EDIM;
    const float x   = r[eb];
    const int k     = lane;

    #pragma unroll
    for (int m = 0; m < 4; m++) {
        float v = fmaf(x, w1[m * 32 + k], b1[m * 32 + k]);
        float mu = warp_sum(v) * (1.f / 32.f);
        float d = v - mu;
        float var = warp_sum(d * d) * (1.f / 32.f);
        v = fmaf(d * rsqrtf(var + 1e-5f), g1[m * 32 + k], be1[m * 32 + k]);
        v = fmaxf(v, 0.f);

        float w2reg[32];
        const float4* w2r = (const float4*)(w2 + (m * 32 + k) * 32);
        #pragma unroll
        for (int q = 0; q < 8; q++) {
            float4 tmp = w2r[q];
            w2reg[q * 4 + 0] = tmp.x; w2reg[q * 4 + 1] = tmp.y;
            w2reg[q * 4 + 2] = tmp.z; w2reg[q * 4 + 3] = tmp.w;
        }
        // 4 parallel chains for latency
        float a0 = b2[m * 32 + k], a1 = 0.f, a2 = 0.f, a3 = 0.f;
        #pragma unroll
        for (int kk = 0; kk < 8; kk++) {
            a0 = fmaf(__shfl_sync(0xffffffffu, v, kk),      w2reg[kk],      a0);
            a1 = fmaf(__shfl_sync(0xffffffffu, v, kk + 8),  w2reg[kk + 8],  a1);
            a2 = fmaf(__shfl_sync(0xffffffffu, v, kk + 16), w2reg[kk + 16], a2);
            a3 = fmaf(__shfl_sync(0xffffffffu, v, kk + 24), w2reg[kk + 24], a3);
        }
        float acc = (a0 + a1) + (a2 + a3);
        float mu2 = warp_sum(acc) * (1.f / 32.f);
        float d2 = acc - mu2;
        float var2 = warp_sum(d2 * d2) * (1.f / 32.f);
        acc = fmaf(d2 * rsqrtf(var2 + 1e-5f), g2[m * 32 + k], be2[m * 32 + k]);
        acc = fmaxf(acc, 0.f);
        h2s[w * H2PAD + m * 32 + k] = acc;
    }

    if (lane < 16) {
        const int j = lane;
        float s0v = src0[eb * 16 + j];
        float s1a = src1[eb * 48 + j * 3 + 0];
        float s1b = src1[eb * 48 + j * 3 + 1];
        float s1c = src1[eb * 48 + j * 3 + 2];
        axA[w * AXPAD + j]      = b00g[node0] * s0v;                 // c00
        axA[w * AXPAD + 16 + j] = s0v;                               // s0
        axA[w * AXPAD + 32 + j] = b10g[node0 * 3 + 0] * s1a          // ws1
                                + b10g[node0 * 3 + 1] * s1b
                                + b10g[node0 * 3 + 2] * s1c;
        if (j < 3) axA[w * AXPAD + 48 + j] = b01g[node0 * 3 + j];
        #pragma unroll
        for (int f = 0; f < 3; f++) {
            float v0 = b11g[node0 * 27 + 0 * 9 + 0 + f] * s1a
                     + b11g[node0 * 27 + 0 * 9 + 3 + f] * s1b
                     + b11g[node0 * 27 + 0 * 9 + 6 + f] * s1c;
            float v1 = b11g[node0 * 27 + 1 * 9 + 0 + f] * s1a
                     + b11g[node0 * 27 + 1 * 9 + 3 + f] * s1b
                     + b11g[node0 * 27 + 1 * 9 + 6 + f] * s1c;
            float v2 = b11g[node0 * 27 + 2 * 9 + 0 + f] * s1a
                     + b11g[node0 * 27 + 2 * 9 + 3 + f] * s1b
                     + b11g[node0 * 27 + 2 * 9 + 6 + f] * s1c;
            v4[w * V11PAD + j * 3 + f] = make_float4(v0, v1, v2, 0.f);
        }
    }
    __syncthreads();

    // ---- main loop: warp = out-channel i; lane = (node, khalf) ----
    const int i     = w;
    const int node  = lane >> 1;
    const int khalf = lane & 1;

    const float* axn = axA + node * AXPAD;
    const float4* v4n = v4 + node * V11PAD;
    const float b01r0 = axn[48], b01r1 = axn[49], b01r2 = axn[50];

    const ulonglong2* hbase =
        (const ulonglong2*)(h2s + node * H2PAD + khalf * 16);
    // m-th h block: hbase + m*8 (ulonglong2 units; 32 floats = 8 u2)

    float z0 = 0.f, y0 = 0.f, y1 = 0.f, y2 = 0.f;
    ulonglong2 hp0, hp1, hp2, hp3;

#define LOAD_HP(m) { const ulonglong2* hp = hbase + (m) * 8; \
    hp0 = hp[0]; hp1 = hp[1]; hp2 = hp[2]; hp3 = hp[3]; }

#define DOT_ROW(slot, gq, SD) \
    float SD; { \
        const int rowq = i * 16 + (gq); \
        const float bb = b3s[(slot) * 256 + rowq]; \
        const ulonglong2* wp = \
            (const ulonglong2*)(Wsm + ((slot) * 256 + rowq) * 32 + khalf * 16); \
        unsigned long long acA = (unsigned long long)__float_as_uint(0.5f * bb); \
        unsigned long long acB = 0ull; \
        ulonglong2 wa = wp[0], wb = wp[1]; \
        ffma2(acA, wa.x, hp0.x); ffma2(acB, wa.y, hp0.y); \
        ffma2(acA, wb.x, hp1.x); ffma2(acB, wb.y, hp1.y); \
        wa = wp[2]; wb = wp[3]; \
        ffma2(acA, wa.x, hp2.x); ffma2(acB, wa.y, hp2.y); \
        ffma2(acA, wb.x, hp3.x); ffma2(acB, wb.y, hp3.y); \
        SD = (__uint_as_float((unsigned)acA) + __uint_as_float((unsigned)(acA >> 32))) \
           + (__uint_as_float((unsigned)acB) + __uint_as_float((unsigned)(acB >> 32))); \
    }

    // ch0: slot0, m0 -> msg0 via c00
    LOAD_HP(0);
    #pragma unroll
    for (int gq = 0; gq < 16; gq++) {
        DOT_ROW(0, gq, s);
        z0 = fmaf(s, axn[gq], z0);
    }
    // ch1: slot1, m1 -> msg1 via s0 * b01[a]
    LOAD_HP(1);
    #pragma unroll
    for (int gq = 0; gq < 16; gq++) {
        DOT_ROW(1, gq, s);
        float tt = s * axn[16 + gq];
        y0 = fmaf(tt, b01r0, y0);
        y1 = fmaf(tt, b01r1, y1);
        y2 = fmaf(tt, b01r2, y2);
    }
    // ch2: slot2, m2 -> msg0 via ws1
    LOAD_HP(2);
    #pragma unroll
    for (int gq = 0; gq < 16; gq++) {
        DOT_ROW(2, gq, s);
        z0 = fmaf(s, axn[32 + gq], z0);
    }
    // ch3..5: slots 3..5, m3 -> msg1 via v11[a][X]
    LOAD_HP(3);
    #pragma unroll
    for (int cc = 0; cc < 3; cc++) {
        #pragma unroll
        for (int gq = 0; gq < 16; gq++) {
            float s;
            if (cc == 0)      { DOT_ROW(3, gq, sx); s = sx; }
            else if (cc == 1) { DOT_ROW(4, gq, sy); s = sy; }
            else              { DOT_ROW(5, gq, sz); s = sz; }
            float4 vv = v4n[cc * 16 + gq];
            y0 = fmaf(s, vv.x, y0);
            y1 = fmaf(s, vv.y, y1);
            y2 = fmaf(s, vv.z, y2);
        }
    }

    // combine k-halves (adjacent lanes), write final messages
    z0 += __shfl_xor_sync(0xffffffffu, z0, 1);
    y0 += __shfl_xor_sync(0xffffffffu, y0, 1);
    y1 += __shfl_xor_sync(0xffffffffu, y1, 1);
    y2 += __shfl_xor_sync(0xffffffffu, y2, 1);

    if (khalf == 0) {
        float* dst = g_msg + (size_t)(blk * NODES + node) * 64;
        dst[i] = z0;
        dst[16 + i * 3 + 0] = y0;
        dst[16 + i * 3 + 1] = y1;
        dst[16 + i * 3 + 2] = y2;
    }
}

// ---- broadcast: per-node message -> 127 edges; no smem, no sync ----
extern "C" __global__ void __launch_bounds__(256)
broadcast_kernel(float4* __restrict__ out)
{
    const int bn = blockIdx.x;
    const int t  = threadIdx.x;
    const float4* mg = (const float4*)(g_msg + (size_t)bn * 64);

    // out0: 508 float4, period 4
    float4 v0 = __ldg(&mg[t & 3]);
    float4* o0 = out + (size_t)bn * 508;
    o0[t] = v0;
    if (t < 252) o0[t + 256] = v0;

    // out1: 1524 float4, period 12; step 256 ≡ +4 (mod 12) -> 3 rotating values
    int s12 = t % 12;
    int sb = s12 + 4; if (sb >= 12) sb -= 12;
    int sc = s12 + 8; if (sc >= 12) sc -= 12;
    float4 va = __ldg(&mg[4 + s12]);
    float4 vb = __ldg(&mg[4 + sb]);
    float4 vc = __ldg(&mg[4 + sc]);

    float4* o1 = out + OUT1_BASE4 + (size_t)bn * 1524;
    o1[t]        = va;
    o1[t + 256]  = vb;
    o1[t + 512]  = vc;
    o1[t + 768]  = va;
    o1[t + 1024] = vb;
    if (t < 244) o1[t + 1280] = vc;
}

extern "C" void kernel_launch(void* const* d_in, const int* in_sizes, int n_in,
                              void* d_out, int out_size)
{
    const float* r    = (const float*)d_in[0];
    const float* src0 = (const float*)d_in[1];
    const float* src1 = (const float*)d_in[2];
    const float* b00  = (const float*)d_in[3];
    const float* b01  = (const float*)d_in[4];
    const float* b10  = (const float*)d_in[5];
    const float* b11  = (const float*)d_in[6];
    const float* w1   = (const float*)d_in[7];
    const float* b1   = (const float*)d_in[8];
    const float* g1   = (const float*)d_in[9];
    const float* be1  = (const float*)d_in[10];
    const float* w2   = (const float*)d_in[11];
    const float* b2   = (const float*)d_in[12];
    const float* g2   = (const float*)d_in[13];
    const float* be2  = (const float*)d_in[14];
    const float* w300 = (const float*)d_in[15];
    const float* b300 = (const float*)d_in[16];
    const float* w301 = (const float*)d_in[17];
    const float* b301 = (const float*)d_in[18];
    const float* w310 = (const float*)d_in[19];
    const float* b310 = (const float*)d_in[20];
    const float* w311 = (const float*)d_in[21];
    const float* b311 = (const float*)d_in[22];

    cudaFuncSetAttribute(compute_kernel,
                         cudaFuncAttributeMaxDynamicSharedMemorySize, SMB);

    compute_kernel<<<GROUPS, CT, SMB>>>(
        r, src0, src1, b00, b01, b10, b11,
        w1, b1, g1, be1, w2, b2, g2, be2,
        w300, b300, w301, b301, w310, b310, w311, b311);

    broadcast_kernel<<<BN, 256>>>((float4*)d_out);
}